// round 1
// baseline (speedup 1.0000x reference)
#include <cuda_runtime.h>
#include <cuda_bf16.h>
#include <math.h>

// ---------------------------------------------------------------------------
// Problem constants
// ---------------------------------------------------------------------------
#define T_SEQ   2048
#define HIDDEN  2048
#define N_HEADS 16
#define N_KV    4
#define HEAD_DIM 128
#define QKV_N   ((N_HEADS + 2 * N_KV) * HEAD_DIM)   // 3072
#define Q_OFF   0
#define K_OFF   (N_HEADS * HEAD_DIM)                 // 2048
#define V_OFF   (K_OFF + N_KV * HEAD_DIM)            // 2560
#define O_DIM   (N_HEADS * HEAD_DIM)                 // 2048

// Scratch (device globals: allocation-free)
__device__ float g_qkv[T_SEQ * QKV_N];     // 24 MB
__device__ float g_attn[T_SEQ * O_DIM];    // 16 MB

// ---------------------------------------------------------------------------
// SGEMM: C[M,N] = A[M,K] @ B[K,N], row-major, fp32.
// BM=128, BN=64, BK=16, 256 threads, 8x4 per-thread tile.
// M % 128 == 0, N % 64 == 0, K % 16 == 0 (true for both call sites).
// ---------------------------------------------------------------------------
#define GBM 128
#define GBN 64
#define GBK 16

__global__ __launch_bounds__(256) void sgemm_kernel(
    const float* __restrict__ A, const float* __restrict__ B,
    float* __restrict__ C, int M, int N, int K)
{
    __shared__ float As[GBK][GBM];   // transposed A tile
    __shared__ float Bs[GBK][GBN];

    const int tid = threadIdx.x;
    const int tx = tid & 15;         // 0..15 -> col group (x4)
    const int ty = tid >> 4;         // 0..15 -> row group (x8)
    const int brow = blockIdx.y * GBM;
    const int bcol = blockIdx.x * GBN;

    // A load: each thread loads 8 floats (2 float4) of one row
    const int a_r  = tid >> 1;             // 0..127
    const int a_k  = (tid & 1) * 8;        // 0 or 8
    // B load: each thread loads 4 floats of one k-row
    const int b_k  = tid >> 4;             // 0..15
    const int b_n  = (tid & 15) * 4;

    float acc[8][4];
#pragma unroll
    for (int i = 0; i < 8; i++)
#pragma unroll
        for (int j = 0; j < 4; j++) acc[i][j] = 0.f;

    for (int k0 = 0; k0 < K; k0 += GBK) {
        float4 a0 = *(const float4*)(A + (size_t)(brow + a_r) * K + k0 + a_k);
        float4 a1 = *(const float4*)(A + (size_t)(brow + a_r) * K + k0 + a_k + 4);
        As[a_k + 0][a_r] = a0.x; As[a_k + 1][a_r] = a0.y;
        As[a_k + 2][a_r] = a0.z; As[a_k + 3][a_r] = a0.w;
        As[a_k + 4][a_r] = a1.x; As[a_k + 5][a_r] = a1.y;
        As[a_k + 6][a_r] = a1.z; As[a_k + 7][a_r] = a1.w;
        *(float4*)(&Bs[b_k][b_n]) = *(const float4*)(B + (size_t)(k0 + b_k) * N + bcol + b_n);
        __syncthreads();

#pragma unroll
        for (int k = 0; k < GBK; k++) {
            float ra[8], rb[4];
            *(float4*)(ra)     = *(float4*)(&As[k][ty * 8]);
            *(float4*)(ra + 4) = *(float4*)(&As[k][ty * 8 + 4]);
            *(float4*)(rb)     = *(float4*)(&Bs[k][tx * 4]);
#pragma unroll
            for (int i = 0; i < 8; i++)
#pragma unroll
                for (int j = 0; j < 4; j++)
                    acc[i][j] = fmaf(ra[i], rb[j], acc[i][j]);
        }
        __syncthreads();
    }

#pragma unroll
    for (int i = 0; i < 8; i++) {
        float4 o = make_float4(acc[i][0], acc[i][1], acc[i][2], acc[i][3]);
        *(float4*)(C + (size_t)(brow + ty * 8 + i) * N + bcol + tx * 4) = o;
    }
}

// ---------------------------------------------------------------------------
// mRoPE: in-place rotation of q (16 heads) and k (4 heads) in g_qkv.
// Output cos/sin index j (0..63): freq index = j; position row:
//   j >= 44 -> row 0 ; j even -> row 1 ; j odd -> row 2
// inv_freq = theta^(-j/64).  Rotation is interleaved pairs (2j, 2j+1).
// ---------------------------------------------------------------------------
__global__ void rope_kernel(const int* __restrict__ positions)
{
    const int t  = blockIdx.x;          // 0..2047
    const int hy = blockIdx.y;          // 0..19  (16 q heads + 4 kv heads)
    const int j  = threadIdx.x;         // 0..63

    const int off = (hy < N_HEADS) ? hy * HEAD_DIM
                                   : K_OFF + (hy - N_HEADS) * HEAD_DIM;
    const int prow = (j >= 44) ? 0 : ((j & 1) ? 2 : 1);
    const float pos = (float)positions[prow * T_SEQ + t];
    // ln(500000) = 13.122363377404328
    const float inv = expf(-((float)j * (1.0f / 64.0f)) * 13.122363377404328f);
    const float ang = pos * inv;
    float sn, cs;
    sincosf(ang, &sn, &cs);

    float* base = g_qkv + (size_t)t * QKV_N + off + 2 * j;
    const float x1 = base[0];
    const float x2 = base[1];
    base[0] = x1 * cs - x2 * sn;
    base[1] = x2 * cs + x1 * sn;
}

// ---------------------------------------------------------------------------
// Causal flash attention, fp32, online softmax.
// grid = (T/32 query tiles, 16 heads), 128 threads.
// Thread t: q = t/4 (query row in tile), quad = t%3..  t&3 (dim/col split).
//   - scores: thread owns key cols c = quad + 4*cc (cc 0..7)
//   - output: thread owns dims quad*32 .. quad*32+31
// smem row stride 132 floats (16B aligned, bank-phase checked).
// ---------------------------------------------------------------------------
#define AT   32          // query & key tile
#define ASTR 132         // padded row stride (floats)
#define ATTN_SMEM_BYTES ((3 * AT * ASTR + AT * 33) * 4)

__global__ __launch_bounds__(128) void attn_kernel()
{
    extern __shared__ float sm[];
    float* Qs = sm;                       // [32][132]
    float* Ks = sm + AT * ASTR;           // [32][132]
    float* Vs = sm + 2 * AT * ASTR;       // [32][132]
    float* Ps = sm + 3 * AT * ASTR;       // [32][33]

    const int tid  = threadIdx.x;
    const int q    = tid >> 2;            // 0..31
    const int quad = tid & 3;             // 0..3
    const int h    = blockIdx.y;
    const int qb   = blockIdx.x;
    const int qg   = qb * AT + q;         // global query row
    const int kvh  = h >> 2;              // GQA: 4 q-heads share a kv-head

    const size_t qrow_base = (size_t)(qb * AT) * QKV_N + h * HEAD_DIM;

    // Load Q tile (32 x 128)
    for (int f = tid; f < AT * 32; f += 128) {
        const int r = f >> 5, c4 = f & 31;
        *(float4*)(Qs + r * ASTR + c4 * 4) =
            *(const float4*)(g_qkv + qrow_base + (size_t)r * QKV_N + c4 * 4);
    }

    float acc[32];
#pragma unroll
    for (int i = 0; i < 32; i++) acc[i] = 0.f;
    float m = -1e30f, l = 0.f;
    const float scale = 0.08838834764831844f;   // 128^-0.5

    for (int j = 0; j <= qb; j++) {
        __syncthreads();   // prior-iteration consumers done (also covers Q load, iter 0)

        // Load K and V tiles for kv head
        const size_t kbase = (size_t)(j * AT) * QKV_N + K_OFF + kvh * HEAD_DIM;
        const size_t vbase = (size_t)(j * AT) * QKV_N + V_OFF + kvh * HEAD_DIM;
        for (int f = tid; f < AT * 32; f += 128) {
            const int r = f >> 5, c4 = f & 31;
            *(float4*)(Ks + r * ASTR + c4 * 4) =
                *(const float4*)(g_qkv + kbase + (size_t)r * QKV_N + c4 * 4);
            *(float4*)(Vs + r * ASTR + c4 * 4) =
                *(const float4*)(g_qkv + vbase + (size_t)r * QKV_N + c4 * 4);
        }
        __syncthreads();

        // ---- scores: 8 cols per thread (c = quad + 4*cc) ----
        float s[8];
#pragma unroll
        for (int cc = 0; cc < 8; cc++) s[cc] = 0.f;
#pragma unroll
        for (int d4 = 0; d4 < 32; d4++) {
            const float4 qv = *(float4*)(Qs + q * ASTR + d4 * 4);
#pragma unroll
            for (int cc = 0; cc < 8; cc++) {
                const int c = quad + 4 * cc;
                const float4 kv = *(float4*)(Ks + c * ASTR + d4 * 4);
                s[cc] += qv.x * kv.x + qv.y * kv.y + qv.z * kv.z + qv.w * kv.w;
            }
        }
        // scale + causal mask
#pragma unroll
        for (int cc = 0; cc < 8; cc++) {
            const int cg = j * AT + quad + 4 * cc;
            s[cc] = (cg > qg) ? -1e30f : s[cc] * scale;
        }

        // ---- online softmax (reduce across quad: lanes 4q..4q+3) ----
        float mx = s[0];
#pragma unroll
        for (int cc = 1; cc < 8; cc++) mx = fmaxf(mx, s[cc]);
        mx = fmaxf(mx, __shfl_xor_sync(0xffffffffu, mx, 1));
        mx = fmaxf(mx, __shfl_xor_sync(0xffffffffu, mx, 2));
        const float mnew = fmaxf(m, mx);
        const float alpha = __expf(m - mnew);

        float lsum = 0.f;
#pragma unroll
        for (int cc = 0; cc < 8; cc++) {
            const float p = __expf(s[cc] - mnew);
            lsum += p;
            Ps[q * 33 + quad + 4 * cc] = p;
        }
        lsum += __shfl_xor_sync(0xffffffffu, lsum, 1);
        lsum += __shfl_xor_sync(0xffffffffu, lsum, 2);
        l = l * alpha + lsum;
        m = mnew;
#pragma unroll
        for (int i = 0; i < 32; i++) acc[i] *= alpha;
        __syncwarp();   // P row q written/read within one warp

        // ---- P @ V: dims quad*32..+31, columns rotated by quad ----
#pragma unroll
        for (int ci = 0; ci < 32; ci++) {
            const int c = (ci + quad) & 31;
            const float p = Ps[q * 33 + c];
#pragma unroll
            for (int d4 = 0; d4 < 8; d4++) {
                const float4 v = *(float4*)(Vs + c * ASTR + quad * 32 + d4 * 4);
                acc[d4 * 4 + 0] = fmaf(p, v.x, acc[d4 * 4 + 0]);
                acc[d4 * 4 + 1] = fmaf(p, v.y, acc[d4 * 4 + 1]);
                acc[d4 * 4 + 2] = fmaf(p, v.z, acc[d4 * 4 + 2]);
                acc[d4 * 4 + 3] = fmaf(p, v.w, acc[d4 * 4 + 3]);
            }
        }
    }

    // Epilogue: normalize and store
    const float inv_l = 1.0f / l;
    float* outp = g_attn + (size_t)qg * O_DIM + h * HEAD_DIM + quad * 32;
#pragma unroll
    for (int d4 = 0; d4 < 8; d4++) {
        float4 o = make_float4(acc[d4 * 4 + 0] * inv_l, acc[d4 * 4 + 1] * inv_l,
                               acc[d4 * 4 + 2] * inv_l, acc[d4 * 4 + 3] * inv_l);
        *(float4*)(outp + d4 * 4) = o;
    }
}

// ---------------------------------------------------------------------------
// Launch
// ---------------------------------------------------------------------------
extern "C" void kernel_launch(void* const* d_in, const int* in_sizes, int n_in,
                              void* d_out, int out_size)
{
    const int*   positions = (const int*)d_in[0];
    const float* hidden    = (const float*)d_in[1];
    const float* w_qkv     = (const float*)d_in[2];
    const float* w_o       = (const float*)d_in[3];
    float*       out       = (float*)d_out;

    float* qkv_ptr;
    float* attn_ptr;
    cudaGetSymbolAddress((void**)&qkv_ptr,  g_qkv);
    cudaGetSymbolAddress((void**)&attn_ptr, g_attn);

    // 1) QKV projection: [2048,2048] @ [2048,3072]
    sgemm_kernel<<<dim3(QKV_N / GBN, T_SEQ / GBM), 256>>>(
        hidden, w_qkv, qkv_ptr, T_SEQ, QKV_N, HIDDEN);

    // 2) mRoPE on q + k heads (in place)
    rope_kernel<<<dim3(T_SEQ, N_HEADS + N_KV), 64>>>(positions);

    // 3) Causal GQA flash attention
    cudaFuncSetAttribute(attn_kernel, cudaFuncAttributeMaxDynamicSharedMemorySize,
                         ATTN_SMEM_BYTES);
    attn_kernel<<<dim3(T_SEQ / AT, N_HEADS), 128, ATTN_SMEM_BYTES>>>();

    // 4) Output projection: [2048,2048] @ [2048,2048]
    sgemm_kernel<<<dim3(O_DIM / GBN, T_SEQ / GBM), 256>>>(
        attn_ptr, w_o, out, T_SEQ, O_DIM, HIDDEN);
}

// round 2
// speedup vs baseline: 4.1511x; 4.1511x over previous
#include <cuda_runtime.h>
#include <cuda_bf16.h>
#include <math.h>
#include <stdint.h>

// ---------------------------------------------------------------------------
// Problem constants
// ---------------------------------------------------------------------------
#define T_SEQ   2048
#define HIDDEN  2048
#define N_HEADS 16
#define N_KV    4
#define HEAD_DIM 128
#define QKV_N   ((N_HEADS + 2 * N_KV) * HEAD_DIM)   // 3072
#define K_OFF   (N_HEADS * HEAD_DIM)                 // 2048
#define V_OFF   (K_OFF + N_KV * HEAD_DIM)            // 2560
#define O_DIM   (N_HEADS * HEAD_DIM)                 // 2048

__device__ float g_qkv[T_SEQ * QKV_N];     // 24 MB scratch
__device__ float g_attn[T_SEQ * O_DIM];    // 16 MB scratch

// ---------------------------------------------------------------------------
// tf32 helpers
// ---------------------------------------------------------------------------
__device__ __forceinline__ uint32_t f2tf32(float x) {
    uint32_t r;
    asm("cvt.rna.tf32.f32 %0, %1;\n" : "=r"(r) : "f"(x));
    return r;
}

__device__ __forceinline__ void mma_tf32(float* d, const uint32_t* a,
                                         const uint32_t* b, const float* c) {
    asm volatile(
        "mma.sync.aligned.m16n8k8.row.col.f32.tf32.tf32.f32 "
        "{%0,%1,%2,%3}, {%4,%5,%6,%7}, {%8,%9}, {%10,%11,%12,%13};\n"
        : "=f"(d[0]), "=f"(d[1]), "=f"(d[2]), "=f"(d[3])
        : "r"(a[0]), "r"(a[1]), "r"(a[2]), "r"(a[3]),
          "r"(b[0]), "r"(b[1]),
          "f"(c[0]), "f"(c[1]), "f"(c[2]), "f"(c[3]));
}

// ---------------------------------------------------------------------------
// tf32 tensor-core GEMM: C[M,N] = A[M,K] @ B[K,N], row-major fp32 in/out.
// 128x128x32 block tile, 256 threads (8 warps, 4x2), warp tile 32x64.
// ---------------------------------------------------------------------------
#define GAS 36     // As row stride (words)
#define GBS 136    // Bs row stride (words)

__global__ __launch_bounds__(256) void gemm_tf32(
    const float* __restrict__ A, const float* __restrict__ B,
    float* __restrict__ C, int M, int N, int K)
{
    __shared__ uint32_t As[128 * GAS];   // [row][k]  128x32
    __shared__ uint32_t Bs[32 * GBS];    // [k][n]    32x128

    const int tid  = threadIdx.x;
    const int lane = tid & 31;
    const int wid  = tid >> 5;
    const int wm   = wid >> 1;      // 0..3
    const int wn   = wid & 1;       // 0..1
    const int lr   = lane >> 2;     // 0..7
    const int lc   = lane & 3;      // 0..3
    const int brow = blockIdx.y * 128;
    const int bcol = blockIdx.x * 128;

    float acc[2][8][4];
#pragma unroll
    for (int mf = 0; mf < 2; mf++)
#pragma unroll
        for (int nf = 0; nf < 8; nf++)
#pragma unroll
            for (int i = 0; i < 4; i++) acc[mf][nf][i] = 0.f;

    for (int k0 = 0; k0 < K; k0 += 32) {
        // A tile: 128x32 floats = 1024 float4, 4 per thread
#pragma unroll
        for (int i = 0; i < 4; i++) {
            const int idx = tid + 256 * i;
            const int r   = idx >> 3;         // 0..127
            const int c4  = (idx & 7) * 4;    // 0..28
            float4 v = *(const float4*)(A + (size_t)(brow + r) * K + k0 + c4);
            uint32_t* p = &As[r * GAS + c4];
            p[0] = f2tf32(v.x); p[1] = f2tf32(v.y);
            p[2] = f2tf32(v.z); p[3] = f2tf32(v.w);
        }
        // B tile: 32x128 floats
#pragma unroll
        for (int i = 0; i < 4; i++) {
            const int idx = tid + 256 * i;
            const int r   = idx >> 5;         // 0..31
            const int c4  = (idx & 31) * 4;   // 0..124
            float4 v = *(const float4*)(B + (size_t)(k0 + r) * N + bcol + c4);
            uint32_t* p = &Bs[r * GBS + c4];
            p[0] = f2tf32(v.x); p[1] = f2tf32(v.y);
            p[2] = f2tf32(v.z); p[3] = f2tf32(v.w);
        }
        __syncthreads();

#pragma unroll
        for (int ks = 0; ks < 4; ks++) {
            const int kk = ks * 8;
            uint32_t af[2][4], bf[8][2];
#pragma unroll
            for (int mf = 0; mf < 2; mf++) {
                const int r = wm * 32 + mf * 16 + lr;
                af[mf][0] = As[r * GAS + kk + lc];
                af[mf][1] = As[(r + 8) * GAS + kk + lc];
                af[mf][2] = As[r * GAS + kk + lc + 4];
                af[mf][3] = As[(r + 8) * GAS + kk + lc + 4];
            }
#pragma unroll
            for (int nf = 0; nf < 8; nf++) {
                const int c = wn * 64 + nf * 8 + lr;
                bf[nf][0] = Bs[(kk + lc) * GBS + c];
                bf[nf][1] = Bs[(kk + lc + 4) * GBS + c];
            }
#pragma unroll
            for (int mf = 0; mf < 2; mf++)
#pragma unroll
                for (int nf = 0; nf < 8; nf++)
                    mma_tf32(acc[mf][nf], af[mf], bf[nf], acc[mf][nf]);
        }
        __syncthreads();
    }

#pragma unroll
    for (int mf = 0; mf < 2; mf++)
#pragma unroll
        for (int nf = 0; nf < 8; nf++) {
            const int r = brow + wm * 32 + mf * 16 + lr;
            const int c = bcol + wn * 64 + nf * 8 + 2 * lc;
            *(float2*)(C + (size_t)r * N + c) =
                make_float2(acc[mf][nf][0], acc[mf][nf][1]);
            *(float2*)(C + (size_t)(r + 8) * N + c) =
                make_float2(acc[mf][nf][2], acc[mf][nf][3]);
        }
}

// ---------------------------------------------------------------------------
// mRoPE (unchanged; in-place on fp32 g_qkv)
// ---------------------------------------------------------------------------
__global__ void rope_kernel(const int* __restrict__ positions)
{
    const int t  = blockIdx.x;
    const int hy = blockIdx.y;          // 0..19
    const int j  = threadIdx.x;         // 0..63

    const int off = (hy < N_HEADS) ? hy * HEAD_DIM
                                   : K_OFF + (hy - N_HEADS) * HEAD_DIM;
    const int prow = (j >= 44) ? 0 : ((j & 1) ? 2 : 1);
    const float pos = (float)positions[prow * T_SEQ + t];
    const float inv = expf(-((float)j * (1.0f / 64.0f)) * 13.122363377404328f);
    const float ang = pos * inv;
    float sn, cs;
    sincosf(ang, &sn, &cs);

    float* base = g_qkv + (size_t)t * QKV_N + off + 2 * j;
    const float x1 = base[0];
    const float x2 = base[1];
    base[0] = x1 * cs - x2 * sn;
    base[1] = x2 * cs + x1 * sn;
}

// ---------------------------------------------------------------------------
// Tensor-core causal flash attention (tf32 mma, fp32 accum/softmax).
// Block: 64 queries x 1 head. 256 threads, warp grid 4(M) x 2(N).
// smem strides (words): Q/K 132, V 136, P 68 -> conflict-free frag loads.
// ---------------------------------------------------------------------------
#define AQS 132
#define AVS 136
#define APS 68
#define ATTN_SMEM_WORDS (64*AQS + 64*AQS + 64*AVS + 64*APS + 2*64)
#define ATTN_SMEM_BYTES (ATTN_SMEM_WORDS * 4)

__global__ __launch_bounds__(256) void attn_tc_kernel()
{
    extern __shared__ uint32_t sm[];
    uint32_t* Qs = sm;                    // [64][132] tf32
    uint32_t* Ks = Qs + 64 * AQS;         // [64][132] tf32  (key-major)
    uint32_t* Vs = Ks + 64 * AQS;         // [64][136] tf32  (key-major)
    uint32_t* Ps = Vs + 64 * AVS;         // [64][68]  tf32
    float*    red = (float*)(Ps + 64 * APS);  // [2][64]

    const int tid  = threadIdx.x;
    const int lane = tid & 31;
    const int wid  = tid >> 5;
    const int wm   = wid >> 1;       // 0..3 : query rows 16*wm
    const int wn   = wid & 1;        // 0..1 : score cols 32*wn / out dims 64*wn
    const int lr   = lane >> 2;
    const int lc   = lane & 3;
    const int h    = blockIdx.y;
    const int qb   = gridDim.x - 1 - blockIdx.x;   // big tiles scheduled first
    const int kvh  = h >> 2;

    // ---- load Q tile (64 x 128) -> tf32 smem ----
#pragma unroll
    for (int i = 0; i < 8; i++) {
        const int idx = tid + 256 * i;
        const int r   = idx >> 5;
        const int c4  = (idx & 31) * 4;
        float4 v = *(const float4*)(g_qkv + (size_t)(qb * 64 + r) * QKV_N
                                    + h * HEAD_DIM + c4);
        uint32_t* p = &Qs[r * AQS + c4];
        p[0] = f2tf32(v.x); p[1] = f2tf32(v.y);
        p[2] = f2tf32(v.z); p[3] = f2tf32(v.w);
    }
    __syncthreads();

    // ---- Q fragments in registers for all 16 k-steps ----
    uint32_t qf[16][4];
    const int qrow = wm * 16 + lr;
#pragma unroll
    for (int ks = 0; ks < 16; ks++) {
        const int kk = ks * 8;
        qf[ks][0] = Qs[qrow * AQS + kk + lc];
        qf[ks][1] = Qs[(qrow + 8) * AQS + kk + lc];
        qf[ks][2] = Qs[qrow * AQS + kk + lc + 4];
        qf[ks][3] = Qs[(qrow + 8) * AQS + kk + lc + 4];
    }

    float m0 = -1e30f, m1 = -1e30f, l0 = 0.f, l1 = 0.f;
    float o[8][4];
#pragma unroll
    for (int nf = 0; nf < 8; nf++)
#pragma unroll
        for (int i = 0; i < 4; i++) o[nf][i] = 0.f;

    const float scale = 0.08838834764831844f;   // 128^-0.5

    for (int j = 0; j <= qb; j++) {
        __syncthreads();   // previous iteration's consumers done
        // ---- load K, V tiles ----
#pragma unroll
        for (int i = 0; i < 8; i++) {
            const int idx = tid + 256 * i;
            const int r   = idx >> 5;
            const int c4  = (idx & 31) * 4;
            const size_t grow = (size_t)(j * 64 + r) * QKV_N + kvh * HEAD_DIM;
            float4 kv = *(const float4*)(g_qkv + grow + K_OFF + c4);
            float4 vv = *(const float4*)(g_qkv + grow + V_OFF + c4);
            uint32_t* pk = &Ks[r * AQS + c4];
            pk[0] = f2tf32(kv.x); pk[1] = f2tf32(kv.y);
            pk[2] = f2tf32(kv.z); pk[3] = f2tf32(kv.w);
            uint32_t* pv = &Vs[r * AVS + c4];
            pv[0] = f2tf32(vv.x); pv[1] = f2tf32(vv.y);
            pv[2] = f2tf32(vv.z); pv[3] = f2tf32(vv.w);
        }
        __syncthreads();

        // ---- scores = Q @ K^T (warp tile 16 x 32) ----
        float sc[4][4];
#pragma unroll
        for (int nf = 0; nf < 4; nf++)
#pragma unroll
            for (int i = 0; i < 4; i++) sc[nf][i] = 0.f;

#pragma unroll
        for (int ks = 0; ks < 16; ks++) {
            const int kk = ks * 8;
            uint32_t bf[4][2];
#pragma unroll
            for (int nf = 0; nf < 4; nf++) {
                const int c = wn * 32 + nf * 8 + lr;   // key index
                bf[nf][0] = Ks[c * AQS + kk + lc];
                bf[nf][1] = Ks[c * AQS + kk + lc + 4];
            }
#pragma unroll
            for (int nf = 0; nf < 4; nf++)
                mma_tf32(sc[nf], qf[ks], bf[nf], sc[nf]);
        }

        // ---- scale + causal mask (diag tile only) ----
        const bool diag = (j == qb);
#pragma unroll
        for (int nf = 0; nf < 4; nf++)
#pragma unroll
            for (int ci = 0; ci < 4; ci++) {
                float s = sc[nf][ci] * scale;
                if (diag) {
                    const int col = wn * 32 + nf * 8 + 2 * lc + (ci & 1);
                    const int row = wm * 16 + lr + ((ci >> 1) * 8);
                    if (col > row) s = -1e30f;
                }
                sc[nf][ci] = s;
            }

        // ---- row max (two row halves per thread) ----
        float mx0 = sc[0][0], mx1 = sc[0][2];
#pragma unroll
        for (int nf = 0; nf < 4; nf++) {
            mx0 = fmaxf(mx0, fmaxf(sc[nf][0], sc[nf][1]));
            mx1 = fmaxf(mx1, fmaxf(sc[nf][2], sc[nf][3]));
        }
        mx0 = fmaxf(mx0, __shfl_xor_sync(0xffffffffu, mx0, 1));
        mx0 = fmaxf(mx0, __shfl_xor_sync(0xffffffffu, mx0, 2));
        mx1 = fmaxf(mx1, __shfl_xor_sync(0xffffffffu, mx1, 1));
        mx1 = fmaxf(mx1, __shfl_xor_sync(0xffffffffu, mx1, 2));

        if (lc == 0) {
            red[wn * 64 + wm * 16 + lr]     = mx0;
            red[wn * 64 + wm * 16 + lr + 8] = mx1;
        }
        __syncthreads();
        const float om0 = red[(1 - wn) * 64 + wm * 16 + lr];
        const float om1 = red[(1 - wn) * 64 + wm * 16 + lr + 8];
        const float mn0 = fmaxf(m0, fmaxf(mx0, om0));
        const float mn1 = fmaxf(m1, fmaxf(mx1, om1));
        const float a0 = __expf(m0 - mn0);
        const float a1 = __expf(m1 - mn1);
        m0 = mn0; m1 = mn1;

        // ---- p = exp(s - m), write P (tf32), partial row sums ----
        float ls0 = 0.f, ls1 = 0.f;
#pragma unroll
        for (int nf = 0; nf < 4; nf++) {
            const float p0 = __expf(sc[nf][0] - mn0);
            const float p1 = __expf(sc[nf][1] - mn0);
            const float p2 = __expf(sc[nf][2] - mn1);
            const float p3 = __expf(sc[nf][3] - mn1);
            ls0 += p0 + p1;
            ls1 += p2 + p3;
            const int c = wn * 32 + nf * 8 + 2 * lc;
            const int r = wm * 16 + lr;
            Ps[r * APS + c]           = f2tf32(p0);
            Ps[r * APS + c + 1]       = f2tf32(p1);
            Ps[(r + 8) * APS + c]     = f2tf32(p2);
            Ps[(r + 8) * APS + c + 1] = f2tf32(p3);
        }
        ls0 += __shfl_xor_sync(0xffffffffu, ls0, 1);
        ls0 += __shfl_xor_sync(0xffffffffu, ls0, 2);
        ls1 += __shfl_xor_sync(0xffffffffu, ls1, 1);
        ls1 += __shfl_xor_sync(0xffffffffu, ls1, 2);
        l0 = l0 * a0 + ls0;
        l1 = l1 * a1 + ls1;

        // ---- rescale output accumulators ----
#pragma unroll
        for (int nf = 0; nf < 8; nf++) {
            o[nf][0] *= a0; o[nf][1] *= a0;
            o[nf][2] *= a1; o[nf][3] *= a1;
        }
        __syncthreads();   // P fully written

        // ---- out += P @ V (warp tile 16 rows x 64 dims) ----
#pragma unroll
        for (int ks = 0; ks < 8; ks++) {
            const int kk = ks * 8;    // key index base
            uint32_t pf[4];
            pf[0] = Ps[(wm * 16 + lr) * APS + kk + lc];
            pf[1] = Ps[(wm * 16 + lr + 8) * APS + kk + lc];
            pf[2] = Ps[(wm * 16 + lr) * APS + kk + lc + 4];
            pf[3] = Ps[(wm * 16 + lr + 8) * APS + kk + lc + 4];
#pragma unroll
            for (int nf = 0; nf < 8; nf++) {
                const int c = wn * 64 + nf * 8 + lr;   // dim index
                uint32_t vf[2];
                vf[0] = Vs[(kk + lc) * AVS + c];
                vf[1] = Vs[(kk + lc + 4) * AVS + c];
                mma_tf32(o[nf], pf, vf, o[nf]);
            }
        }
    }

    // ---- epilogue: combine l across warp-column pair, normalize, store ----
    __syncthreads();
    if (lc == 0) {
        red[wn * 64 + wm * 16 + lr]     = l0;
        red[wn * 64 + wm * 16 + lr + 8] = l1;
    }
    __syncthreads();
    const float lt0 = l0 + red[(1 - wn) * 64 + wm * 16 + lr];
    const float lt1 = l1 + red[(1 - wn) * 64 + wm * 16 + lr + 8];
    const float i0 = 1.0f / lt0;
    const float i1 = 1.0f / lt1;

#pragma unroll
    for (int nf = 0; nf < 8; nf++) {
        const int r = qb * 64 + wm * 16 + lr;
        const int c = h * HEAD_DIM + wn * 64 + nf * 8 + 2 * lc;
        *(float2*)(g_attn + (size_t)r * O_DIM + c) =
            make_float2(o[nf][0] * i0, o[nf][1] * i0);
        *(float2*)(g_attn + (size_t)(r + 8) * O_DIM + c) =
            make_float2(o[nf][2] * i1, o[nf][3] * i1);
    }
}

// ---------------------------------------------------------------------------
// Launch
// ---------------------------------------------------------------------------
extern "C" void kernel_launch(void* const* d_in, const int* in_sizes, int n_in,
                              void* d_out, int out_size)
{
    const int*   positions = (const int*)d_in[0];
    const float* hidden    = (const float*)d_in[1];
    const float* w_qkv     = (const float*)d_in[2];
    const float* w_o       = (const float*)d_in[3];
    float*       out       = (float*)d_out;

    float* qkv_ptr;
    float* attn_ptr;
    cudaGetSymbolAddress((void**)&qkv_ptr,  g_qkv);
    cudaGetSymbolAddress((void**)&attn_ptr, g_attn);

    // 1) QKV projection: [2048,2048] @ [2048,3072]
    gemm_tf32<<<dim3(QKV_N / 128, T_SEQ / 128), 256>>>(
        hidden, w_qkv, qkv_ptr, T_SEQ, QKV_N, HIDDEN);

    // 2) mRoPE (in place)
    rope_kernel<<<dim3(T_SEQ, N_HEADS + N_KV), 64>>>(positions);

    // 3) Tensor-core causal flash attention
    static int attn_cfg = 0;
    if (!attn_cfg) {
        cudaFuncSetAttribute(attn_tc_kernel,
                             cudaFuncAttributeMaxDynamicSharedMemorySize,
                             ATTN_SMEM_BYTES);
        attn_cfg = 1;
    }
    attn_tc_kernel<<<dim3(T_SEQ / 64, N_HEADS), 256, ATTN_SMEM_BYTES>>>();

    // 4) Output projection: [2048,2048] @ [2048,2048]
    gemm_tf32<<<dim3(O_DIM / 128, T_SEQ / 128), 256>>>(
        attn_ptr, w_o, out, T_SEQ, O_DIM, HIDDEN);
}

// round 3
// speedup vs baseline: 4.6307x; 1.1156x over previous
#include <cuda_runtime.h>
#include <cuda_bf16.h>
#include <math.h>
#include <stdint.h>

// ---------------------------------------------------------------------------
// Problem constants
// ---------------------------------------------------------------------------
#define T_SEQ   2048
#define HIDDEN  2048
#define N_HEADS 16
#define N_KV    4
#define HEAD_DIM 128
#define QKV_N   ((N_HEADS + 2 * N_KV) * HEAD_DIM)   // 3072
#define K_OFF   (N_HEADS * HEAD_DIM)                 // 2048
#define V_OFF   (K_OFF + N_KV * HEAD_DIM)            // 2560
#define O_DIM   (N_HEADS * HEAD_DIM)                 // 2048

__device__ float g_qkv[T_SEQ * QKV_N];     // 24 MB scratch
__device__ float g_attn[T_SEQ * O_DIM];    // 16 MB scratch

// ---------------------------------------------------------------------------
// helpers
// ---------------------------------------------------------------------------
__device__ __forceinline__ uint32_t f2tf32(float x) {
    uint32_t r;
    asm("cvt.rna.tf32.f32 %0, %1;\n" : "=r"(r) : "f"(x));
    return r;
}
__device__ __forceinline__ uint32_t u2tf32(uint32_t x) {
    return f2tf32(__uint_as_float(x));
}
__device__ __forceinline__ void mma_tf32(float* d, const uint32_t* a,
                                         const uint32_t* b, const float* c) {
    asm volatile(
        "mma.sync.aligned.m16n8k8.row.col.f32.tf32.tf32.f32 "
        "{%0,%1,%2,%3}, {%4,%5,%6,%7}, {%8,%9}, {%10,%11,%12,%13};\n"
        : "=f"(d[0]), "=f"(d[1]), "=f"(d[2]), "=f"(d[3])
        : "r"(a[0]), "r"(a[1]), "r"(a[2]), "r"(a[3]),
          "r"(b[0]), "r"(b[1]),
          "f"(c[0]), "f"(c[1]), "f"(c[2]), "f"(c[3]));
}
__device__ __forceinline__ void cp16(uint32_t saddr, const void* g) {
    asm volatile("cp.async.cg.shared.global [%0], [%1], 16;\n"
                 :: "r"(saddr), "l"(g));
}
__device__ __forceinline__ void cp_commit() {
    asm volatile("cp.async.commit_group;\n" ::: "memory");
}
__device__ __forceinline__ void cp_wait0() {
    asm volatile("cp.async.wait_group 0;\n" ::: "memory");
}
__device__ __forceinline__ uint32_t s2u(const void* p) {
    return (uint32_t)__cvta_generic_to_shared(p);
}

// ---------------------------------------------------------------------------
// tf32 tensor-core GEMM, cp.async double-buffered.
// C[M,N] = A[M,K] @ B[K,N], row-major fp32. 128x128x32 tile, 256 threads.
// Raw fp32 staged in smem; tf32 conversion on the fragment-load path.
// ---------------------------------------------------------------------------
#define GAS 36     // As row stride (words)
#define GBS 136    // Bs row stride (words)
#define GEMM_SMEM_BYTES ((2 * 128 * GAS + 2 * 32 * GBS) * 4)

__global__ __launch_bounds__(256, 2) void gemm_tf32(
    const float* __restrict__ A, const float* __restrict__ B,
    float* __restrict__ C, int M, int N, int K)
{
    extern __shared__ uint32_t sh[];
    uint32_t* As = sh;                    // [2][128*GAS]
    uint32_t* Bs = sh + 2 * 128 * GAS;    // [2][32*GBS]

    const int tid  = threadIdx.x;
    const int lane = tid & 31;
    const int wid  = tid >> 5;
    const int wm   = wid >> 1;      // 0..3
    const int wn   = wid & 1;       // 0..1
    const int lr   = lane >> 2;     // 0..7
    const int lc   = lane & 3;      // 0..3
    const int brow = blockIdx.y * 128;
    const int bcol = blockIdx.x * 128;

    // per-thread load coordinates
    const int ar = tid >> 3;             // +32 per chunk... (idx>>3)
    const int ac = (tid & 7) * 4;
    const int br = tid >> 5;             // +8 per chunk
    const int bc = (tid & 31) * 4;

    const uint32_t as_base = s2u(As);
    const uint32_t bs_base = s2u(Bs);

    float acc[2][8][4];
#pragma unroll
    for (int mf = 0; mf < 2; mf++)
#pragma unroll
        for (int nf = 0; nf < 8; nf++)
#pragma unroll
            for (int i = 0; i < 4; i++) acc[mf][nf][i] = 0.f;

    const int ntk = K >> 5;

#define GEMM_ISSUE(KT, BUF)                                                    \
    do {                                                                       \
        const int k0 = (KT) * 32;                                              \
        const uint32_t abuf = as_base + (BUF) * 128 * GAS * 4;                 \
        const uint32_t bbuf = bs_base + (BUF) * 32 * GBS * 4;                  \
        _Pragma("unroll")                                                      \
        for (int i = 0; i < 4; i++) {                                          \
            const int r = ar + 32 * i;                                         \
            cp16(abuf + (r * GAS + ac) * 4,                                    \
                 A + (size_t)(brow + r) * K + k0 + ac);                        \
        }                                                                      \
        _Pragma("unroll")                                                      \
        for (int i = 0; i < 4; i++) {                                          \
            const int r = br + 8 * i;                                          \
            cp16(bbuf + (r * GBS + bc) * 4,                                    \
                 B + (size_t)(k0 + r) * N + bcol + bc);                        \
        }                                                                      \
        cp_commit();                                                           \
    } while (0)

    GEMM_ISSUE(0, 0);

    for (int kt = 0; kt < ntk; kt++) {
        cp_wait0();
        __syncthreads();
        if (kt + 1 < ntk) GEMM_ISSUE(kt + 1, (kt + 1) & 1);

        const uint32_t* Ab = As + (kt & 1) * 128 * GAS;
        const uint32_t* Bb = Bs + (kt & 1) * 32 * GBS;

#pragma unroll
        for (int ks = 0; ks < 4; ks++) {
            const int kk = ks * 8;
            uint32_t af[2][4], bf[8][2];
#pragma unroll
            for (int mf = 0; mf < 2; mf++) {
                const int r = wm * 32 + mf * 16 + lr;
                af[mf][0] = u2tf32(Ab[r * GAS + kk + lc]);
                af[mf][1] = u2tf32(Ab[(r + 8) * GAS + kk + lc]);
                af[mf][2] = u2tf32(Ab[r * GAS + kk + lc + 4]);
                af[mf][3] = u2tf32(Ab[(r + 8) * GAS + kk + lc + 4]);
            }
#pragma unroll
            for (int nf = 0; nf < 8; nf++) {
                const int c = wn * 64 + nf * 8 + lr;
                bf[nf][0] = u2tf32(Bb[(kk + lc) * GBS + c]);
                bf[nf][1] = u2tf32(Bb[(kk + lc + 4) * GBS + c]);
            }
#pragma unroll
            for (int mf = 0; mf < 2; mf++)
#pragma unroll
                for (int nf = 0; nf < 8; nf++)
                    mma_tf32(acc[mf][nf], af[mf], bf[nf], acc[mf][nf]);
        }
    }

#pragma unroll
    for (int mf = 0; mf < 2; mf++)
#pragma unroll
        for (int nf = 0; nf < 8; nf++) {
            const int r = brow + wm * 32 + mf * 16 + lr;
            const int c = bcol + wn * 64 + nf * 8 + 2 * lc;
            *(float2*)(C + (size_t)r * N + c) =
                make_float2(acc[mf][nf][0], acc[mf][nf][1]);
            *(float2*)(C + (size_t)(r + 8) * N + c) =
                make_float2(acc[mf][nf][2], acc[mf][nf][3]);
        }
#undef GEMM_ISSUE
}

// ---------------------------------------------------------------------------
// mRoPE (in-place on fp32 g_qkv)
// ---------------------------------------------------------------------------
__global__ void rope_kernel(const int* __restrict__ positions)
{
    const int t  = blockIdx.x;
    const int hy = blockIdx.y;          // 0..19
    const int j  = threadIdx.x;         // 0..63

    const int off = (hy < N_HEADS) ? hy * HEAD_DIM
                                   : K_OFF + (hy - N_HEADS) * HEAD_DIM;
    const int prow = (j >= 44) ? 0 : ((j & 1) ? 2 : 1);
    const float pos = (float)positions[prow * T_SEQ + t];
    const float inv = expf(-((float)j * (1.0f / 64.0f)) * 13.122363377404328f);
    const float ang = pos * inv;
    float sn, cs;
    sincosf(ang, &sn, &cs);

    float* base = g_qkv + (size_t)t * QKV_N + off + 2 * j;
    const float x1 = base[0];
    const float x2 = base[1];
    base[0] = x1 * cs - x2 * sn;
    base[1] = x2 * cs + x1 * sn;
}

// ---------------------------------------------------------------------------
// Tensor-core causal flash attention, cp.async double-buffered K/V.
// Block: 64 queries x 1 head. 256 threads, warp grid 4(M) x 2(N).
// K/V staged raw fp32 (K stride 132, V stride 136), tf32 cvt at frag load.
// ---------------------------------------------------------------------------
#define AQS 132
#define AVS 136
#define APS 68
#define ATTN_SMEM_WORDS (64*AQS + 2*64*AQS + 2*64*AVS + 64*APS + 128)
#define ATTN_SMEM_BYTES (ATTN_SMEM_WORDS * 4)

__global__ __launch_bounds__(256) void attn_tc_kernel()
{
    extern __shared__ uint32_t sm[];
    uint32_t* Qs = sm;                        // [64][132] tf32
    uint32_t* Kr = Qs + 64 * AQS;             // [2][64][132] raw fp32
    uint32_t* Vr = Kr + 2 * 64 * AQS;         // [2][64][136] raw fp32
    uint32_t* Ps = Vr + 2 * 64 * AVS;         // [64][68]  tf32
    float*    red = (float*)(Ps + 64 * APS);  // [2][64]

    const int tid  = threadIdx.x;
    const int lane = tid & 31;
    const int wid  = tid >> 5;
    const int wm   = wid >> 1;       // 0..3 : query rows 16*wm
    const int wn   = wid & 1;        // 0..1 : score cols 32*wn / out dims 64*wn
    const int lr   = lane >> 2;
    const int lc   = lane & 3;
    const int h    = blockIdx.y;
    const int qb   = gridDim.x - 1 - blockIdx.x;   // big tiles first
    const int kvh  = h >> 2;

    const uint32_t kr_base = s2u(Kr);
    const uint32_t vr_base = s2u(Vr);
    const int ldr = tid >> 5;              // 0..7  (+8 per chunk)
    const int ldc = (tid & 31) * 4;

#define ATTN_ISSUE(J, BUF)                                                     \
    do {                                                                       \
        const uint32_t kb = kr_base + (BUF) * 64 * AQS * 4;                    \
        const uint32_t vb = vr_base + (BUF) * 64 * AVS * 4;                    \
        _Pragma("unroll")                                                      \
        for (int i = 0; i < 8; i++) {                                          \
            const int r = ldr + 8 * i;                                         \
            const size_t grow = (size_t)((J) * 64 + r) * QKV_N                 \
                                + kvh * HEAD_DIM + ldc;                        \
            cp16(kb + (r * AQS + ldc) * 4, g_qkv + grow + K_OFF);              \
            cp16(vb + (r * AVS + ldc) * 4, g_qkv + grow + V_OFF);              \
        }                                                                      \
        cp_commit();                                                           \
    } while (0)

    // kick off KV tile 0 while loading Q
    ATTN_ISSUE(0, 0);

    // ---- load Q tile (64 x 128) -> tf32 smem ----
#pragma unroll
    for (int i = 0; i < 8; i++) {
        const int r = ldr + 8 * i;
        float4 v = *(const float4*)(g_qkv + (size_t)(qb * 64 + r) * QKV_N
                                    + h * HEAD_DIM + ldc);
        uint32_t* p = &Qs[r * AQS + ldc];
        p[0] = f2tf32(v.x); p[1] = f2tf32(v.y);
        p[2] = f2tf32(v.z); p[3] = f2tf32(v.w);
    }
    __syncthreads();

    // ---- Q fragments in registers for all 16 k-steps ----
    uint32_t qf[16][4];
    const int qrow = wm * 16 + lr;
#pragma unroll
    for (int ks = 0; ks < 16; ks++) {
        const int kk = ks * 8;
        qf[ks][0] = Qs[qrow * AQS + kk + lc];
        qf[ks][1] = Qs[(qrow + 8) * AQS + kk + lc];
        qf[ks][2] = Qs[qrow * AQS + kk + lc + 4];
        qf[ks][3] = Qs[(qrow + 8) * AQS + kk + lc + 4];
    }

    float m0 = -1e30f, m1 = -1e30f, l0 = 0.f, l1 = 0.f;
    float o[8][4];
#pragma unroll
    for (int nf = 0; nf < 8; nf++)
#pragma unroll
        for (int i = 0; i < 4; i++) o[nf][i] = 0.f;

    const float scale = 0.08838834764831844f;   // 128^-0.5

    for (int j = 0; j <= qb; j++) {
        cp_wait0();
        __syncthreads();                       // KV(j) visible; prev P/V reads done
        if (j < qb) ATTN_ISSUE(j + 1, (j + 1) & 1);

        const uint32_t* Kb = Kr + (j & 1) * 64 * AQS;
        const uint32_t* Vb = Vr + (j & 1) * 64 * AVS;

        // ---- scores = Q @ K^T (warp tile 16 x 32) ----
        float sc[4][4];
#pragma unroll
        for (int nf = 0; nf < 4; nf++)
#pragma unroll
            for (int i = 0; i < 4; i++) sc[nf][i] = 0.f;

#pragma unroll
        for (int ks = 0; ks < 16; ks++) {
            const int kk = ks * 8;
            uint32_t bf[4][2];
#pragma unroll
            for (int nf = 0; nf < 4; nf++) {
                const int c = wn * 32 + nf * 8 + lr;   // key index
                bf[nf][0] = u2tf32(Kb[c * AQS + kk + lc]);
                bf[nf][1] = u2tf32(Kb[c * AQS + kk + lc + 4]);
            }
#pragma unroll
            for (int nf = 0; nf < 4; nf++)
                mma_tf32(sc[nf], qf[ks], bf[nf], sc[nf]);
        }

        // ---- scale + causal mask (diag tile only) ----
        const bool diag = (j == qb);
#pragma unroll
        for (int nf = 0; nf < 4; nf++)
#pragma unroll
            for (int ci = 0; ci < 4; ci++) {
                float s = sc[nf][ci] * scale;
                if (diag) {
                    const int col = wn * 32 + nf * 8 + 2 * lc + (ci & 1);
                    const int row = wm * 16 + lr + ((ci >> 1) * 8);
                    if (col > row) s = -1e30f;
                }
                sc[nf][ci] = s;
            }

        // ---- row max ----
        float mx0 = sc[0][0], mx1 = sc[0][2];
#pragma unroll
        for (int nf = 0; nf < 4; nf++) {
            mx0 = fmaxf(mx0, fmaxf(sc[nf][0], sc[nf][1]));
            mx1 = fmaxf(mx1, fmaxf(sc[nf][2], sc[nf][3]));
        }
        mx0 = fmaxf(mx0, __shfl_xor_sync(0xffffffffu, mx0, 1));
        mx0 = fmaxf(mx0, __shfl_xor_sync(0xffffffffu, mx0, 2));
        mx1 = fmaxf(mx1, __shfl_xor_sync(0xffffffffu, mx1, 1));
        mx1 = fmaxf(mx1, __shfl_xor_sync(0xffffffffu, mx1, 2));

        if (lc == 0) {
            red[wn * 64 + wm * 16 + lr]     = mx0;
            red[wn * 64 + wm * 16 + lr + 8] = mx1;
        }
        __syncthreads();
        const float om0 = red[(1 - wn) * 64 + wm * 16 + lr];
        const float om1 = red[(1 - wn) * 64 + wm * 16 + lr + 8];
        const float mn0 = fmaxf(m0, fmaxf(mx0, om0));
        const float mn1 = fmaxf(m1, fmaxf(mx1, om1));
        const float a0 = __expf(m0 - mn0);
        const float a1 = __expf(m1 - mn1);
        m0 = mn0; m1 = mn1;

        // ---- p = exp(s - m), write P (tf32), partial row sums ----
        float ls0 = 0.f, ls1 = 0.f;
#pragma unroll
        for (int nf = 0; nf < 4; nf++) {
            const float p0 = __expf(sc[nf][0] - mn0);
            const float p1 = __expf(sc[nf][1] - mn0);
            const float p2 = __expf(sc[nf][2] - mn1);
            const float p3 = __expf(sc[nf][3] - mn1);
            ls0 += p0 + p1;
            ls1 += p2 + p3;
            const int c = wn * 32 + nf * 8 + 2 * lc;
            const int r = wm * 16 + lr;
            Ps[r * APS + c]           = f2tf32(p0);
            Ps[r * APS + c + 1]       = f2tf32(p1);
            Ps[(r + 8) * APS + c]     = f2tf32(p2);
            Ps[(r + 8) * APS + c + 1] = f2tf32(p3);
        }
        ls0 += __shfl_xor_sync(0xffffffffu, ls0, 1);
        ls0 += __shfl_xor_sync(0xffffffffu, ls0, 2);
        ls1 += __shfl_xor_sync(0xffffffffu, ls1, 1);
        ls1 += __shfl_xor_sync(0xffffffffu, ls1, 2);
        l0 = l0 * a0 + ls0;
        l1 = l1 * a1 + ls1;

        // ---- rescale output accumulators ----
#pragma unroll
        for (int nf = 0; nf < 8; nf++) {
            o[nf][0] *= a0; o[nf][1] *= a0;
            o[nf][2] *= a1; o[nf][3] *= a1;
        }
        __syncthreads();   // P fully written

        // ---- out += P @ V (warp tile 16 rows x 64 dims) ----
#pragma unroll
        for (int ks = 0; ks < 8; ks++) {
            const int kk = ks * 8;    // key index base
            uint32_t pf[4];
            pf[0] = Ps[(wm * 16 + lr) * APS + kk + lc];
            pf[1] = Ps[(wm * 16 + lr + 8) * APS + kk + lc];
            pf[2] = Ps[(wm * 16 + lr) * APS + kk + lc + 4];
            pf[3] = Ps[(wm * 16 + lr + 8) * APS + kk + lc + 4];
#pragma unroll
            for (int nf = 0; nf < 8; nf++) {
                const int c = wn * 64 + nf * 8 + lr;   // dim index
                uint32_t vf[2];
                vf[0] = u2tf32(Vb[(kk + lc) * AVS + c]);
                vf[1] = u2tf32(Vb[(kk + lc + 4) * AVS + c]);
                mma_tf32(o[nf], pf, vf, o[nf]);
            }
        }
    }
#undef ATTN_ISSUE

    // ---- epilogue: combine l across warp-column pair, normalize, store ----
    __syncthreads();
    if (lc == 0) {
        red[wn * 64 + wm * 16 + lr]     = l0;
        red[wn * 64 + wm * 16 + lr + 8] = l1;
    }
    __syncthreads();
    const float lt0 = l0 + red[(1 - wn) * 64 + wm * 16 + lr];
    const float lt1 = l1 + red[(1 - wn) * 64 + wm * 16 + lr + 8];
    const float i0 = 1.0f / lt0;
    const float i1 = 1.0f / lt1;

#pragma unroll
    for (int nf = 0; nf < 8; nf++) {
        const int r = qb * 64 + wm * 16 + lr;
        const int c = h * HEAD_DIM + wn * 64 + nf * 8 + 2 * lc;
        *(float2*)(g_attn + (size_t)r * O_DIM + c) =
            make_float2(o[nf][0] * i0, o[nf][1] * i0);
        *(float2*)(g_attn + (size_t)(r + 8) * O_DIM + c) =
            make_float2(o[nf][2] * i1, o[nf][3] * i1);
    }
}

// ---------------------------------------------------------------------------
// Launch
// ---------------------------------------------------------------------------
extern "C" void kernel_launch(void* const* d_in, const int* in_sizes, int n_in,
                              void* d_out, int out_size)
{
    const int*   positions = (const int*)d_in[0];
    const float* hidden    = (const float*)d_in[1];
    const float* w_qkv     = (const float*)d_in[2];
    const float* w_o       = (const float*)d_in[3];
    float*       out       = (float*)d_out;

    float* qkv_ptr;
    float* attn_ptr;
    cudaGetSymbolAddress((void**)&qkv_ptr,  g_qkv);
    cudaGetSymbolAddress((void**)&attn_ptr, g_attn);

    static int cfg = 0;
    if (!cfg) {
        cudaFuncSetAttribute(gemm_tf32,
                             cudaFuncAttributeMaxDynamicSharedMemorySize,
                             GEMM_SMEM_BYTES);
        cudaFuncSetAttribute(attn_tc_kernel,
                             cudaFuncAttributeMaxDynamicSharedMemorySize,
                             ATTN_SMEM_BYTES);
        cfg = 1;
    }

    // 1) QKV projection: [2048,2048] @ [2048,3072]
    gemm_tf32<<<dim3(QKV_N / 128, T_SEQ / 128), 256, GEMM_SMEM_BYTES>>>(
        hidden, w_qkv, qkv_ptr, T_SEQ, QKV_N, HIDDEN);

    // 2) mRoPE (in place)
    rope_kernel<<<dim3(T_SEQ, N_HEADS + N_KV), 64>>>(positions);

    // 3) Tensor-core causal flash attention
    attn_tc_kernel<<<dim3(T_SEQ / 64, N_HEADS), 256, ATTN_SMEM_BYTES>>>();

    // 4) Output projection: [2048,2048] @ [2048,2048]
    gemm_tf32<<<dim3(O_DIM / 128, T_SEQ / 128), 256, GEMM_SMEM_BYTES>>>(
        attn_ptr, w_o, out, T_SEQ, O_DIM, HIDDEN);
}

// round 4
// speedup vs baseline: 4.8084x; 1.0384x over previous
#include <cuda_runtime.h>
#include <cuda_bf16.h>
#include <math.h>
#include <stdint.h>

// ---------------------------------------------------------------------------
// Problem constants
// ---------------------------------------------------------------------------
#define T_SEQ   2048
#define HIDDEN  2048
#define N_HEADS 16
#define N_KV    4
#define HEAD_DIM 128
#define QKV_N   ((N_HEADS + 2 * N_KV) * HEAD_DIM)   // 3072
#define K_OFF   (N_HEADS * HEAD_DIM)                 // 2048
#define V_OFF   (K_OFF + N_KV * HEAD_DIM)            // 2560
#define O_DIM   (N_HEADS * HEAD_DIM)                 // 2048

__device__ float g_qkv[T_SEQ * QKV_N];      // 24 MB
__device__ float g_attn[T_SEQ * O_DIM];     // 16 MB (tf32-rounded by attn)
__device__ float g_hid_r[T_SEQ * HIDDEN];   // 16 MB rounded hidden
__device__ float g_wqkv_r[HIDDEN * QKV_N];  // 24 MB rounded w_qkv
__device__ float g_wo_r[O_DIM * HIDDEN];    // 16 MB rounded w_o

// ---------------------------------------------------------------------------
// helpers
// ---------------------------------------------------------------------------
__device__ __forceinline__ uint32_t f2tf32(float x) {
    uint32_t r;
    asm("cvt.rna.tf32.f32 %0, %1;\n" : "=r"(r) : "f"(x));
    return r;
}
__device__ __forceinline__ float roundtf(float x) {
    return __uint_as_float(f2tf32(x));
}
__device__ __forceinline__ void mma_tf32(float* d, const uint32_t* a,
                                         const uint32_t* b, const float* c) {
    asm volatile(
        "mma.sync.aligned.m16n8k8.row.col.f32.tf32.tf32.f32 "
        "{%0,%1,%2,%3}, {%4,%5,%6,%7}, {%8,%9}, {%10,%11,%12,%13};\n"
        : "=f"(d[0]), "=f"(d[1]), "=f"(d[2]), "=f"(d[3])
        : "r"(a[0]), "r"(a[1]), "r"(a[2]), "r"(a[3]),
          "r"(b[0]), "r"(b[1]),
          "f"(c[0]), "f"(c[1]), "f"(c[2]), "f"(c[3]));
}
__device__ __forceinline__ void cp16(uint32_t saddr, const void* g) {
    asm volatile("cp.async.cg.shared.global [%0], [%1], 16;\n"
                 :: "r"(saddr), "l"(g));
}
__device__ __forceinline__ void cp_commit() {
    asm volatile("cp.async.commit_group;\n" ::: "memory");
}
__device__ __forceinline__ void cp_wait0() {
    asm volatile("cp.async.wait_group 0;\n" ::: "memory");
}
__device__ __forceinline__ uint32_t s2u(const void* p) {
    return (uint32_t)__cvta_generic_to_shared(p);
}

// ---------------------------------------------------------------------------
// tf32 round-copy: dst[i] = round_tf32(src[i]); n divisible by 1024
// ---------------------------------------------------------------------------
__global__ __launch_bounds__(256) void round_tf32_kernel(
    const float4* __restrict__ src, float4* __restrict__ dst)
{
    const int i = blockIdx.x * 256 + threadIdx.x;
    float4 v = src[i];
    v.x = roundtf(v.x); v.y = roundtf(v.y);
    v.z = roundtf(v.z); v.w = roundtf(v.w);
    dst[i] = v;
}

// ---------------------------------------------------------------------------
// tf32 tensor-core GEMM, cp.async double-buffered. Inputs pre-rounded to
// tf32 (low mantissa bits zero) -> no cvt in the mainloop.
// C[M,N] = A[M,K] @ B[K,N], 128x128x32 tile, 256 threads.
// ---------------------------------------------------------------------------
#define GAS 36     // As row stride (words)
#define GBS 136    // Bs row stride (words)
#define GEMM_SMEM_BYTES ((2 * 128 * GAS + 2 * 32 * GBS) * 4)

__global__ __launch_bounds__(256, 2) void gemm_tf32(
    const float* __restrict__ A, const float* __restrict__ B,
    float* __restrict__ C, int M, int N, int K)
{
    extern __shared__ uint32_t sh[];
    uint32_t* As = sh;                    // [2][128*GAS]
    uint32_t* Bs = sh + 2 * 128 * GAS;    // [2][32*GBS]

    const int tid  = threadIdx.x;
    const int lane = tid & 31;
    const int wid  = tid >> 5;
    const int wm   = wid >> 1;      // 0..3
    const int wn   = wid & 1;       // 0..1
    const int lr   = lane >> 2;     // 0..7
    const int lc   = lane & 3;      // 0..3
    const int brow = blockIdx.y * 128;
    const int bcol = blockIdx.x * 128;

    const int ar = tid >> 3;
    const int ac = (tid & 7) * 4;
    const int br = tid >> 5;
    const int bc = (tid & 31) * 4;

    const uint32_t as_base = s2u(As);
    const uint32_t bs_base = s2u(Bs);

    float acc[2][8][4];
#pragma unroll
    for (int mf = 0; mf < 2; mf++)
#pragma unroll
        for (int nf = 0; nf < 8; nf++)
#pragma unroll
            for (int i = 0; i < 4; i++) acc[mf][nf][i] = 0.f;

    const int ntk = K >> 5;

#define GEMM_ISSUE(KT, BUF)                                                    \
    do {                                                                       \
        const int k0 = (KT) * 32;                                              \
        const uint32_t abuf = as_base + (BUF) * 128 * GAS * 4;                 \
        const uint32_t bbuf = bs_base + (BUF) * 32 * GBS * 4;                  \
        _Pragma("unroll")                                                      \
        for (int i = 0; i < 4; i++) {                                          \
            const int r = ar + 32 * i;                                         \
            cp16(abuf + (r * GAS + ac) * 4,                                    \
                 A + (size_t)(brow + r) * K + k0 + ac);                        \
        }                                                                      \
        _Pragma("unroll")                                                      \
        for (int i = 0; i < 4; i++) {                                          \
            const int r = br + 8 * i;                                          \
            cp16(bbuf + (r * GBS + bc) * 4,                                    \
                 B + (size_t)(k0 + r) * N + bcol + bc);                        \
        }                                                                      \
        cp_commit();                                                           \
    } while (0)

    GEMM_ISSUE(0, 0);

    for (int kt = 0; kt < ntk; kt++) {
        cp_wait0();
        __syncthreads();
        if (kt + 1 < ntk) GEMM_ISSUE(kt + 1, (kt + 1) & 1);

        const uint32_t* Ab = As + (kt & 1) * 128 * GAS;
        const uint32_t* Bb = Bs + (kt & 1) * 32 * GBS;

#pragma unroll
        for (int ks = 0; ks < 4; ks++) {
            const int kk = ks * 8;
            uint32_t af[2][4], bf[8][2];
#pragma unroll
            for (int mf = 0; mf < 2; mf++) {
                const int r = wm * 32 + mf * 16 + lr;
                af[mf][0] = Ab[r * GAS + kk + lc];
                af[mf][1] = Ab[(r + 8) * GAS + kk + lc];
                af[mf][2] = Ab[r * GAS + kk + lc + 4];
                af[mf][3] = Ab[(r + 8) * GAS + kk + lc + 4];
            }
#pragma unroll
            for (int nf = 0; nf < 8; nf++) {
                const int c = wn * 64 + nf * 8 + lr;
                bf[nf][0] = Bb[(kk + lc) * GBS + c];
                bf[nf][1] = Bb[(kk + lc + 4) * GBS + c];
            }
#pragma unroll
            for (int mf = 0; mf < 2; mf++)
#pragma unroll
                for (int nf = 0; nf < 8; nf++)
                    mma_tf32(acc[mf][nf], af[mf], bf[nf], acc[mf][nf]);
        }
    }

#pragma unroll
    for (int mf = 0; mf < 2; mf++)
#pragma unroll
        for (int nf = 0; nf < 8; nf++) {
            const int r = brow + wm * 32 + mf * 16 + lr;
            const int c = bcol + wn * 64 + nf * 8 + 2 * lc;
            *(float2*)(C + (size_t)r * N + c) =
                make_float2(acc[mf][nf][0], acc[mf][nf][1]);
            *(float2*)(C + (size_t)(r + 8) * N + c) =
                make_float2(acc[mf][nf][2], acc[mf][nf][3]);
        }
#undef GEMM_ISSUE
}

// ---------------------------------------------------------------------------
// mRoPE + tf32 pre-round. hy 0..15: Q heads (rotate+round),
// 16..19: K heads (rotate+round), 20..23: V heads (round only).
// ---------------------------------------------------------------------------
__global__ void rope_kernel(const int* __restrict__ positions)
{
    const int t  = blockIdx.x;
    const int hy = blockIdx.y;          // 0..23
    const int j  = threadIdx.x;         // 0..63

    if (hy >= 20) {   // V: round only
        float* base = g_qkv + (size_t)t * QKV_N + V_OFF
                      + (hy - 20) * HEAD_DIM + 2 * j;
        base[0] = roundtf(base[0]);
        base[1] = roundtf(base[1]);
        return;
    }

    const int off = (hy < N_HEADS) ? hy * HEAD_DIM
                                   : K_OFF + (hy - N_HEADS) * HEAD_DIM;
    const int prow = (j >= 44) ? 0 : ((j & 1) ? 2 : 1);
    const float pos = (float)positions[prow * T_SEQ + t];
    const float inv = expf(-((float)j * (1.0f / 64.0f)) * 13.122363377404328f);
    const float ang = pos * inv;
    float sn, cs;
    sincosf(ang, &sn, &cs);

    float* base = g_qkv + (size_t)t * QKV_N + off + 2 * j;
    const float x1 = base[0];
    const float x2 = base[1];
    base[0] = roundtf(x1 * cs - x2 * sn);
    base[1] = roundtf(x2 * cs + x1 * sn);
}

// ---------------------------------------------------------------------------
// Tensor-core causal flash attention, cp.async double-buffered K/V.
// All inputs pre-rounded tf32 -> cvt only on the P path.
// ---------------------------------------------------------------------------
#define AQS 132
#define AVS 136
#define APS 68
#define ATTN_SMEM_WORDS (64*AQS + 2*64*AQS + 2*64*AVS + 64*APS + 128)
#define ATTN_SMEM_BYTES (ATTN_SMEM_WORDS * 4)

__global__ __launch_bounds__(256) void attn_tc_kernel()
{
    extern __shared__ uint32_t sm[];
    uint32_t* Qs = sm;                        // [64][132]
    uint32_t* Kr = Qs + 64 * AQS;             // [2][64][132]
    uint32_t* Vr = Kr + 2 * 64 * AQS;         // [2][64][136]
    uint32_t* Ps = Vr + 2 * 64 * AVS;         // [64][68]
    float*    red = (float*)(Ps + 64 * APS);  // [2][64]

    const int tid  = threadIdx.x;
    const int lane = tid & 31;
    const int wid  = tid >> 5;
    const int wm   = wid >> 1;
    const int wn   = wid & 1;
    const int lr   = lane >> 2;
    const int lc   = lane & 3;
    const int h    = blockIdx.y;
    const int qb   = gridDim.x - 1 - blockIdx.x;   // big tiles first
    const int kvh  = h >> 2;

    const uint32_t kr_base = s2u(Kr);
    const uint32_t vr_base = s2u(Vr);
    const int ldr = tid >> 5;              // 0..7  (+8 per chunk)
    const int ldc = (tid & 31) * 4;

#define ATTN_ISSUE(J, BUF)                                                     \
    do {                                                                       \
        const uint32_t kb = kr_base + (BUF) * 64 * AQS * 4;                    \
        const uint32_t vb = vr_base + (BUF) * 64 * AVS * 4;                    \
        _Pragma("unroll")                                                      \
        for (int i = 0; i < 8; i++) {                                          \
            const int r = ldr + 8 * i;                                         \
            const size_t grow = (size_t)((J) * 64 + r) * QKV_N                 \
                                + kvh * HEAD_DIM + ldc;                        \
            cp16(kb + (r * AQS + ldc) * 4, g_qkv + grow + K_OFF);              \
            cp16(vb + (r * AVS + ldc) * 4, g_qkv + grow + V_OFF);              \
        }                                                                      \
        cp_commit();                                                           \
    } while (0)

    // KV tile 0 + Q tile via cp.async
    ATTN_ISSUE(0, 0);
    {
        const uint32_t qs_base = s2u(Qs);
#pragma unroll
        for (int i = 0; i < 8; i++) {
            const int r = ldr + 8 * i;
            cp16(qs_base + (r * AQS + ldc) * 4,
                 g_qkv + (size_t)(qb * 64 + r) * QKV_N + h * HEAD_DIM + ldc);
        }
        cp_commit();
    }
    cp_wait0();
    __syncthreads();

    // ---- Q fragments in registers for all 16 k-steps ----
    uint32_t qf[16][4];
    const int qrow = wm * 16 + lr;
#pragma unroll
    for (int ks = 0; ks < 16; ks++) {
        const int kk = ks * 8;
        qf[ks][0] = Qs[qrow * AQS + kk + lc];
        qf[ks][1] = Qs[(qrow + 8) * AQS + kk + lc];
        qf[ks][2] = Qs[qrow * AQS + kk + lc + 4];
        qf[ks][3] = Qs[(qrow + 8) * AQS + kk + lc + 4];
    }

    float m0 = -1e30f, m1 = -1e30f, l0 = 0.f, l1 = 0.f;
    float o[8][4];
#pragma unroll
    for (int nf = 0; nf < 8; nf++)
#pragma unroll
        for (int i = 0; i < 4; i++) o[nf][i] = 0.f;

    const float scale = 0.08838834764831844f;   // 128^-0.5

    for (int j = 0; j <= qb; j++) {
        cp_wait0();
        __syncthreads();                       // KV(j) visible; prev reads done
        if (j < qb) ATTN_ISSUE(j + 1, (j + 1) & 1);

        const uint32_t* Kb = Kr + (j & 1) * 64 * AQS;
        const uint32_t* Vb = Vr + (j & 1) * 64 * AVS;

        // ---- scores = Q @ K^T (warp tile 16 x 32) ----
        float sc[4][4];
#pragma unroll
        for (int nf = 0; nf < 4; nf++)
#pragma unroll
            for (int i = 0; i < 4; i++) sc[nf][i] = 0.f;

#pragma unroll
        for (int ks = 0; ks < 16; ks++) {
            const int kk = ks * 8;
            uint32_t bf[4][2];
#pragma unroll
            for (int nf = 0; nf < 4; nf++) {
                const int c = wn * 32 + nf * 8 + lr;
                bf[nf][0] = Kb[c * AQS + kk + lc];
                bf[nf][1] = Kb[c * AQS + kk + lc + 4];
            }
#pragma unroll
            for (int nf = 0; nf < 4; nf++)
                mma_tf32(sc[nf], qf[ks], bf[nf], sc[nf]);
        }

        // ---- scale + causal mask (diag tile only) ----
        const bool diag = (j == qb);
#pragma unroll
        for (int nf = 0; nf < 4; nf++)
#pragma unroll
            for (int ci = 0; ci < 4; ci++) {
                float s = sc[nf][ci] * scale;
                if (diag) {
                    const int col = wn * 32 + nf * 8 + 2 * lc + (ci & 1);
                    const int row = wm * 16 + lr + ((ci >> 1) * 8);
                    if (col > row) s = -1e30f;
                }
                sc[nf][ci] = s;
            }

        // ---- row max ----
        float mx0 = sc[0][0], mx1 = sc[0][2];
#pragma unroll
        for (int nf = 0; nf < 4; nf++) {
            mx0 = fmaxf(mx0, fmaxf(sc[nf][0], sc[nf][1]));
            mx1 = fmaxf(mx1, fmaxf(sc[nf][2], sc[nf][3]));
        }
        mx0 = fmaxf(mx0, __shfl_xor_sync(0xffffffffu, mx0, 1));
        mx0 = fmaxf(mx0, __shfl_xor_sync(0xffffffffu, mx0, 2));
        mx1 = fmaxf(mx1, __shfl_xor_sync(0xffffffffu, mx1, 1));
        mx1 = fmaxf(mx1, __shfl_xor_sync(0xffffffffu, mx1, 2));

        if (lc == 0) {
            red[wn * 64 + wm * 16 + lr]     = mx0;
            red[wn * 64 + wm * 16 + lr + 8] = mx1;
        }
        __syncthreads();
        const float om0 = red[(1 - wn) * 64 + wm * 16 + lr];
        const float om1 = red[(1 - wn) * 64 + wm * 16 + lr + 8];
        const float mn0 = fmaxf(m0, fmaxf(mx0, om0));
        const float mn1 = fmaxf(m1, fmaxf(mx1, om1));
        const float a0 = __expf(m0 - mn0);
        const float a1 = __expf(m1 - mn1);
        m0 = mn0; m1 = mn1;

        // ---- p = exp(s - m), write P (tf32), partial row sums ----
        float ls0 = 0.f, ls1 = 0.f;
#pragma unroll
        for (int nf = 0; nf < 4; nf++) {
            const float p0 = __expf(sc[nf][0] - mn0);
            const float p1 = __expf(sc[nf][1] - mn0);
            const float p2 = __expf(sc[nf][2] - mn1);
            const float p3 = __expf(sc[nf][3] - mn1);
            ls0 += p0 + p1;
            ls1 += p2 + p3;
            const int c = wn * 32 + nf * 8 + 2 * lc;
            const int r = wm * 16 + lr;
            Ps[r * APS + c]           = f2tf32(p0);
            Ps[r * APS + c + 1]       = f2tf32(p1);
            Ps[(r + 8) * APS + c]     = f2tf32(p2);
            Ps[(r + 8) * APS + c + 1] = f2tf32(p3);
        }
        ls0 += __shfl_xor_sync(0xffffffffu, ls0, 1);
        ls0 += __shfl_xor_sync(0xffffffffu, ls0, 2);
        ls1 += __shfl_xor_sync(0xffffffffu, ls1, 1);
        ls1 += __shfl_xor_sync(0xffffffffu, ls1, 2);
        l0 = l0 * a0 + ls0;
        l1 = l1 * a1 + ls1;

        // ---- rescale output accumulators ----
#pragma unroll
        for (int nf = 0; nf < 8; nf++) {
            o[nf][0] *= a0; o[nf][1] *= a0;
            o[nf][2] *= a1; o[nf][3] *= a1;
        }
        __syncthreads();   // P fully written

        // ---- out += P @ V (warp tile 16 rows x 64 dims) ----
#pragma unroll
        for (int ks = 0; ks < 8; ks++) {
            const int kk = ks * 8;
            uint32_t pf[4];
            pf[0] = Ps[(wm * 16 + lr) * APS + kk + lc];
            pf[1] = Ps[(wm * 16 + lr + 8) * APS + kk + lc];
            pf[2] = Ps[(wm * 16 + lr) * APS + kk + lc + 4];
            pf[3] = Ps[(wm * 16 + lr + 8) * APS + kk + lc + 4];
#pragma unroll
            for (int nf = 0; nf < 8; nf++) {
                const int c = wn * 64 + nf * 8 + lr;
                uint32_t vf[2];
                vf[0] = Vb[(kk + lc) * AVS + c];
                vf[1] = Vb[(kk + lc + 4) * AVS + c];
                mma_tf32(o[nf], pf, vf, o[nf]);
            }
        }
    }
#undef ATTN_ISSUE

    // ---- epilogue: combine l, normalize, round to tf32, store ----
    __syncthreads();
    if (lc == 0) {
        red[wn * 64 + wm * 16 + lr]     = l0;
        red[wn * 64 + wm * 16 + lr + 8] = l1;
    }
    __syncthreads();
    const float lt0 = l0 + red[(1 - wn) * 64 + wm * 16 + lr];
    const float lt1 = l1 + red[(1 - wn) * 64 + wm * 16 + lr + 8];
    const float i0 = 1.0f / lt0;
    const float i1 = 1.0f / lt1;

#pragma unroll
    for (int nf = 0; nf < 8; nf++) {
        const int r = qb * 64 + wm * 16 + lr;
        const int c = h * HEAD_DIM + wn * 64 + nf * 8 + 2 * lc;
        *(float2*)(g_attn + (size_t)r * O_DIM + c) =
            make_float2(roundtf(o[nf][0] * i0), roundtf(o[nf][1] * i0));
        *(float2*)(g_attn + (size_t)(r + 8) * O_DIM + c) =
            make_float2(roundtf(o[nf][2] * i1), roundtf(o[nf][3] * i1));
    }
}

// ---------------------------------------------------------------------------
// Launch
// ---------------------------------------------------------------------------
extern "C" void kernel_launch(void* const* d_in, const int* in_sizes, int n_in,
                              void* d_out, int out_size)
{
    const int*   positions = (const int*)d_in[0];
    const float* hidden    = (const float*)d_in[1];
    const float* w_qkv     = (const float*)d_in[2];
    const float* w_o       = (const float*)d_in[3];
    float*       out       = (float*)d_out;

    float *qkv_ptr, *attn_ptr, *hid_ptr, *wqkv_ptr, *wo_ptr;
    cudaGetSymbolAddress((void**)&qkv_ptr,  g_qkv);
    cudaGetSymbolAddress((void**)&attn_ptr, g_attn);
    cudaGetSymbolAddress((void**)&hid_ptr,  g_hid_r);
    cudaGetSymbolAddress((void**)&wqkv_ptr, g_wqkv_r);
    cudaGetSymbolAddress((void**)&wo_ptr,   g_wo_r);

    static int cfg = 0;
    if (!cfg) {
        cudaFuncSetAttribute(gemm_tf32,
                             cudaFuncAttributeMaxDynamicSharedMemorySize,
                             GEMM_SMEM_BYTES);
        cudaFuncSetAttribute(attn_tc_kernel,
                             cudaFuncAttributeMaxDynamicSharedMemorySize,
                             ATTN_SMEM_BYTES);
        cfg = 1;
    }

    // 0) tf32 pre-round of GEMM inputs
    round_tf32_kernel<<<(T_SEQ * HIDDEN) / 1024, 256>>>(
        (const float4*)hidden, (float4*)hid_ptr);
    round_tf32_kernel<<<(HIDDEN * QKV_N) / 1024, 256>>>(
        (const float4*)w_qkv, (float4*)wqkv_ptr);
    round_tf32_kernel<<<(O_DIM * HIDDEN) / 1024, 256>>>(
        (const float4*)w_o, (float4*)wo_ptr);

    // 1) QKV projection
    gemm_tf32<<<dim3(QKV_N / 128, T_SEQ / 128), 256, GEMM_SMEM_BYTES>>>(
        hid_ptr, wqkv_ptr, qkv_ptr, T_SEQ, QKV_N, HIDDEN);

    // 2) mRoPE + V rounding
    rope_kernel<<<dim3(T_SEQ, N_HEADS + 2 * N_KV), 64>>>(positions);

    // 3) Tensor-core causal flash attention
    attn_tc_kernel<<<dim3(T_SEQ / 64, N_HEADS), 256, ATTN_SMEM_BYTES>>>();

    // 4) Output projection
    gemm_tf32<<<dim3(O_DIM / 128, T_SEQ / 128), 256, GEMM_SMEM_BYTES>>>(
        attn_ptr, wo_ptr, out, T_SEQ, O_DIM, HIDDEN);
}

// round 6
// speedup vs baseline: 4.9355x; 1.0264x over previous
#include <cuda_runtime.h>
#include <cuda_bf16.h>
#include <math.h>
#include <stdint.h>

// ---------------------------------------------------------------------------
// Problem constants
// ---------------------------------------------------------------------------
#define T_SEQ   2048
#define HIDDEN  2048
#define N_HEADS 16
#define N_KV    4
#define HEAD_DIM 128
#define QKV_N   ((N_HEADS + 2 * N_KV) * HEAD_DIM)   // 3072
#define K_OFF   (N_HEADS * HEAD_DIM)                 // 2048
#define V_OFF   (K_OFF + N_KV * HEAD_DIM)            // 2560
#define O_DIM   (N_HEADS * HEAD_DIM)                 // 2048

__device__ float g_qkv[T_SEQ * QKV_N];      // 24 MB
__device__ float g_attn[T_SEQ * O_DIM];     // 16 MB (tf32-rounded by attn)
__device__ float g_hid_r[T_SEQ * HIDDEN];   // rounded hidden
__device__ float g_wqkv_r[HIDDEN * QKV_N];  // rounded w_qkv [K,N]
__device__ float g_wo_r[O_DIM * HIDDEN];    // rounded w_o   [K,N]

// ---------------------------------------------------------------------------
// helpers
// ---------------------------------------------------------------------------
__device__ __forceinline__ uint32_t f2tf32(float x) {
    uint32_t r;
    asm("cvt.rna.tf32.f32 %0, %1;\n" : "=r"(r) : "f"(x));
    return r;
}
__device__ __forceinline__ float roundtf(float x) {
    return __uint_as_float(f2tf32(x));
}
__device__ __forceinline__ void mma_tf32(float* d, const uint32_t* a,
                                         const uint32_t* b, const float* c) {
    asm volatile(
        "mma.sync.aligned.m16n8k8.row.col.f32.tf32.tf32.f32 "
        "{%0,%1,%2,%3}, {%4,%5,%6,%7}, {%8,%9}, {%10,%11,%12,%13};\n"
        : "=f"(d[0]), "=f"(d[1]), "=f"(d[2]), "=f"(d[3])
        : "r"(a[0]), "r"(a[1]), "r"(a[2]), "r"(a[3]),
          "r"(b[0]), "r"(b[1]),
          "f"(c[0]), "f"(c[1]), "f"(c[2]), "f"(c[3]));
}
__device__ __forceinline__ void cp16(uint32_t saddr, const void* g) {
    asm volatile("cp.async.cg.shared.global [%0], [%1], 16;\n"
                 :: "r"(saddr), "l"(g));
}
__device__ __forceinline__ void cp_commit() {
    asm volatile("cp.async.commit_group;\n" ::: "memory");
}
__device__ __forceinline__ void cp_wait0() {
    asm volatile("cp.async.wait_group 0;\n" ::: "memory");
}
__device__ __forceinline__ uint32_t s2u(const void* p) {
    return (uint32_t)__cvta_generic_to_shared(p);
}

// ---------------------------------------------------------------------------
// tf32 round-copy
// ---------------------------------------------------------------------------
__global__ __launch_bounds__(256) void round_tf32_kernel(
    const float4* __restrict__ src, float4* __restrict__ dst)
{
    const int i = blockIdx.x * 256 + threadIdx.x;
    float4 v = src[i];
    v.x = roundtf(v.x); v.y = roundtf(v.y);
    v.z = roundtf(v.z); v.w = roundtf(v.w);
    dst[i] = v;
}

// ---------------------------------------------------------------------------
// tf32 tensor-core GEMM (R4 version, known-good).
// C[M,N] = A[M,K] @ B[K,N], 128x128x32 tile, 256 threads, cp.async 2-stage.
// ---------------------------------------------------------------------------
#define GAS 36
#define GBS 136
#define GEMM_SMEM_BYTES ((2 * 128 * GAS + 2 * 32 * GBS) * 4)

__global__ __launch_bounds__(256, 2) void gemm_tf32(
    const float* __restrict__ A, const float* __restrict__ B,
    float* __restrict__ C, int M, int N, int K)
{
    extern __shared__ uint32_t sh[];
    uint32_t* As = sh;
    uint32_t* Bs = sh + 2 * 128 * GAS;

    const int tid  = threadIdx.x;
    const int lane = tid & 31;
    const int wid  = tid >> 5;
    const int wm   = wid >> 1;
    const int wn   = wid & 1;
    const int lr   = lane >> 2;
    const int lc   = lane & 3;
    const int brow = blockIdx.y * 128;
    const int bcol = blockIdx.x * 128;

    const int ar = tid >> 3;
    const int ac = (tid & 7) * 4;
    const int br = tid >> 5;
    const int bc = (tid & 31) * 4;

    const uint32_t as_base = s2u(As);
    const uint32_t bs_base = s2u(Bs);

    float acc[2][8][4];
#pragma unroll
    for (int mf = 0; mf < 2; mf++)
#pragma unroll
        for (int nf = 0; nf < 8; nf++)
#pragma unroll
            for (int i = 0; i < 4; i++) acc[mf][nf][i] = 0.f;

    const int ntk = K >> 5;

#define GEMM_ISSUE(KT, BUF)                                                    \
    do {                                                                       \
        const int k0 = (KT) * 32;                                              \
        const uint32_t abuf = as_base + (BUF) * 128 * GAS * 4;                 \
        const uint32_t bbuf = bs_base + (BUF) * 32 * GBS * 4;                  \
        _Pragma("unroll")                                                      \
        for (int i = 0; i < 4; i++) {                                          \
            const int r = ar + 32 * i;                                         \
            cp16(abuf + (r * GAS + ac) * 4,                                    \
                 A + (size_t)(brow + r) * K + k0 + ac);                        \
        }                                                                      \
        _Pragma("unroll")                                                      \
        for (int i = 0; i < 4; i++) {                                          \
            const int r = br + 8 * i;                                          \
            cp16(bbuf + (r * GBS + bc) * 4,                                    \
                 B + (size_t)(k0 + r) * N + bcol + bc);                        \
        }                                                                      \
        cp_commit();                                                           \
    } while (0)

    GEMM_ISSUE(0, 0);

    for (int kt = 0; kt < ntk; kt++) {
        cp_wait0();
        __syncthreads();
        if (kt + 1 < ntk) GEMM_ISSUE(kt + 1, (kt + 1) & 1);

        const uint32_t* Ab = As + (kt & 1) * 128 * GAS;
        const uint32_t* Bb = Bs + (kt & 1) * 32 * GBS;

#pragma unroll
        for (int ks = 0; ks < 4; ks++) {
            const int kk = ks * 8;
            uint32_t af[2][4], bf[8][2];
#pragma unroll
            for (int mf = 0; mf < 2; mf++) {
                const int r = wm * 32 + mf * 16 + lr;
                af[mf][0] = Ab[r * GAS + kk + lc];
                af[mf][1] = Ab[(r + 8) * GAS + kk + lc];
                af[mf][2] = Ab[r * GAS + kk + lc + 4];
                af[mf][3] = Ab[(r + 8) * GAS + kk + lc + 4];
            }
#pragma unroll
            for (int nf = 0; nf < 8; nf++) {
                const int c = wn * 64 + nf * 8 + lr;
                bf[nf][0] = Bb[(kk + lc) * GBS + c];
                bf[nf][1] = Bb[(kk + lc + 4) * GBS + c];
            }
#pragma unroll
            for (int mf = 0; mf < 2; mf++)
#pragma unroll
                for (int nf = 0; nf < 8; nf++)
                    mma_tf32(acc[mf][nf], af[mf], bf[nf], acc[mf][nf]);
        }
    }

#pragma unroll
    for (int mf = 0; mf < 2; mf++)
#pragma unroll
        for (int nf = 0; nf < 8; nf++) {
            const int r = brow + wm * 32 + mf * 16 + lr;
            const int c = bcol + wn * 64 + nf * 8 + 2 * lc;
            *(float2*)(C + (size_t)r * N + c) =
                make_float2(acc[mf][nf][0], acc[mf][nf][1]);
            *(float2*)(C + (size_t)(r + 8) * N + c) =
                make_float2(acc[mf][nf][2], acc[mf][nf][3]);
        }
#undef GEMM_ISSUE
}

// ---------------------------------------------------------------------------
// mRoPE + tf32 pre-round (Q/K rotate+round, V round only)
// ---------------------------------------------------------------------------
__global__ void rope_kernel(const int* __restrict__ positions)
{
    const int t  = blockIdx.x;
    const int hy = blockIdx.y;          // 0..23
    const int j  = threadIdx.x;         // 0..63

    if (hy >= 20) {
        float* base = g_qkv + (size_t)t * QKV_N + V_OFF
                      + (hy - 20) * HEAD_DIM + 2 * j;
        base[0] = roundtf(base[0]);
        base[1] = roundtf(base[1]);
        return;
    }

    const int off = (hy < N_HEADS) ? hy * HEAD_DIM
                                   : K_OFF + (hy - N_HEADS) * HEAD_DIM;
    const int prow = (j >= 44) ? 0 : ((j & 1) ? 2 : 1);
    const float pos = (float)positions[prow * T_SEQ + t];
    const float inv = expf(-((float)j * (1.0f / 64.0f)) * 13.122363377404328f);
    const float ang = pos * inv;
    float sn, cs;
    sincosf(ang, &sn, &cs);

    float* base = g_qkv + (size_t)t * QKV_N + off + 2 * j;
    const float x1 = base[0];
    const float x2 = base[1];
    base[0] = roundtf(x1 * cs - x2 * sn);
    base[1] = roundtf(x2 * cs + x1 * sn);
}

// ---------------------------------------------------------------------------
// Causal flash attention, warp-owns-full-rows layout.
// Block: 128 queries x 1 head, 256 threads, 8 warps x 16 rows.
// KV tiles 64 x 128, cp.async double-buffered; ONE syncthreads per tile.
// Softmax fully warp-local; P passes QK->PV via register shfl-transpose.
// ---------------------------------------------------------------------------
#define AKS 132
#define AVS 136
#define ATTN_SMEM_WORDS (2 * 64 * AKS + 2 * 64 * AVS)
#define ATTN_SMEM_BYTES (ATTN_SMEM_WORDS * 4)

__global__ __launch_bounds__(256) void attn_tc_kernel()
{
    extern __shared__ uint32_t sm[];
    uint32_t* Kr = sm;                 // [2][64][132]
    uint32_t* Vr = Kr + 2 * 64 * AKS;  // [2][64][136]

    const int tid  = threadIdx.x;
    const int lane = tid & 31;
    const int wid  = tid >> 5;         // 0..7 : query rows 16*wid
    const int lr   = lane >> 2;
    const int lc   = lane & 3;
    const int h    = blockIdx.y;
    const int qb   = gridDim.x - 1 - blockIdx.x;   // big tiles first
    const int kvh  = h >> 2;

    const int row0 = qb * 128 + wid * 16 + lr;     // thread's row (half 0)

    const uint32_t kr_base = s2u(Kr);
    const uint32_t vr_base = s2u(Vr);
    const int ldr = tid >> 5;
    const int ldc = (tid & 31) * 4;

#define ATTN_ISSUE(J, BUF)                                                     \
    do {                                                                       \
        const uint32_t kb = kr_base + (BUF) * 64 * AKS * 4;                    \
        const uint32_t vb = vr_base + (BUF) * 64 * AVS * 4;                    \
        _Pragma("unroll")                                                      \
        for (int i = 0; i < 8; i++) {                                          \
            const int r = ldr + 8 * i;                                         \
            const size_t grow = (size_t)((J) * 64 + r) * QKV_N                 \
                                + kvh * HEAD_DIM + ldc;                        \
            cp16(kb + (r * AKS + ldc) * 4, g_qkv + grow + K_OFF);              \
            cp16(vb + (r * AVS + ldc) * 4, g_qkv + grow + V_OFF);              \
        }                                                                      \
        cp_commit();                                                           \
    } while (0)

    ATTN_ISSUE(0, 0);

    // ---- Q fragments straight from gmem (pre-rounded by rope) ----
    uint32_t qf[16][4];
    {
        const float* q0 = g_qkv + (size_t)row0 * QKV_N + h * HEAD_DIM;
        const float* q8 = q0 + 8 * (size_t)QKV_N;
#pragma unroll
        for (int ks = 0; ks < 16; ks++) {
            qf[ks][0] = __float_as_uint(q0[8 * ks + lc]);
            qf[ks][1] = __float_as_uint(q8[8 * ks + lc]);
            qf[ks][2] = __float_as_uint(q0[8 * ks + lc + 4]);
            qf[ks][3] = __float_as_uint(q8[8 * ks + lc + 4]);
        }
    }

    float m0 = -1e30f, m1 = -1e30f, l0 = 0.f, l1 = 0.f;
    float o[16][4];
#pragma unroll
    for (int nf = 0; nf < 16; nf++)
#pragma unroll
        for (int i = 0; i < 4; i++) o[nf][i] = 0.f;

    const float scale = 0.08838834764831844f;   // 128^-0.5
    const int jmax = 2 * qb + 1;
    const int wrow_lo = qb * 128 + wid * 16;     // warp's min row

    for (int j = 0; j <= jmax; j++) {
        cp_wait0();
        __syncthreads();                         // tile j ready, prev reads done
        if (j < jmax) ATTN_ISSUE(j + 1, (j + 1) & 1);

        const bool active = (64 * j <= wrow_lo + 15);  // some col unmasked?
        if (active) {
            const uint32_t* Kb = Kr + (j & 1) * 64 * AKS;
            const uint32_t* Vb = Vr + (j & 1) * 64 * AVS;

            // ---- scores = Q @ K^T : warp tile 16 x 64 ----
            float sc[8][4];
#pragma unroll
            for (int nf = 0; nf < 8; nf++)
#pragma unroll
                for (int i = 0; i < 4; i++) sc[nf][i] = 0.f;

#pragma unroll
            for (int ks = 0; ks < 16; ks++) {
                const int kk = ks * 8;
                uint32_t bf[8][2];
#pragma unroll
                for (int nf = 0; nf < 8; nf++) {
                    const int c = nf * 8 + lr;
                    bf[nf][0] = Kb[c * AKS + kk + lc];
                    bf[nf][1] = Kb[c * AKS + kk + lc + 4];
                }
#pragma unroll
                for (int nf = 0; nf < 8; nf++)
                    mma_tf32(sc[nf], qf[ks], bf[nf], sc[nf]);
            }

            // ---- scale + causal mask ----
            const bool needmask = (64 * j + 63 > wrow_lo);
#pragma unroll
            for (int nf = 0; nf < 8; nf++)
#pragma unroll
                for (int ci = 0; ci < 4; ci++) {
                    float s = sc[nf][ci] * scale;
                    if (needmask) {
                        const int col = 64 * j + nf * 8 + 2 * lc + (ci & 1);
                        const int row = row0 + ((ci >> 1) * 8);
                        if (col > row) s = -1e30f;
                    }
                    sc[nf][ci] = s;
                }

            // ---- warp-local row max ----
            float mx0 = sc[0][0], mx1 = sc[0][2];
#pragma unroll
            for (int nf = 0; nf < 8; nf++) {
                mx0 = fmaxf(mx0, fmaxf(sc[nf][0], sc[nf][1]));
                mx1 = fmaxf(mx1, fmaxf(sc[nf][2], sc[nf][3]));
            }
            mx0 = fmaxf(mx0, __shfl_xor_sync(0xffffffffu, mx0, 1));
            mx0 = fmaxf(mx0, __shfl_xor_sync(0xffffffffu, mx0, 2));
            mx1 = fmaxf(mx1, __shfl_xor_sync(0xffffffffu, mx1, 1));
            mx1 = fmaxf(mx1, __shfl_xor_sync(0xffffffffu, mx1, 2));

            const float mn0 = fmaxf(m0, mx0);
            const float mn1 = fmaxf(m1, mx1);
            const float a0 = __expf(m0 - mn0);
            const float a1 = __expf(m1 - mn1);
            m0 = mn0; m1 = mn1;

            // ---- p = exp(s - m) in place; row sums ----
            float ls0 = 0.f, ls1 = 0.f;
#pragma unroll
            for (int nf = 0; nf < 8; nf++) {
                sc[nf][0] = __expf(sc[nf][0] - mn0);
                sc[nf][1] = __expf(sc[nf][1] - mn0);
                sc[nf][2] = __expf(sc[nf][2] - mn1);
                sc[nf][3] = __expf(sc[nf][3] - mn1);
                ls0 += sc[nf][0] + sc[nf][1];
                ls1 += sc[nf][2] + sc[nf][3];
            }
            ls0 += __shfl_xor_sync(0xffffffffu, ls0, 1);
            ls0 += __shfl_xor_sync(0xffffffffu, ls0, 2);
            ls1 += __shfl_xor_sync(0xffffffffu, ls1, 1);
            ls1 += __shfl_xor_sync(0xffffffffu, ls1, 2);
            l0 = l0 * a0 + ls0;
            l1 = l1 * a1 + ls1;

            // ---- rescale output accumulators ----
#pragma unroll
            for (int nf = 0; nf < 16; nf++) {
                o[nf][0] *= a0; o[nf][1] *= a0;
                o[nf][2] *= a1; o[nf][3] *= a1;
            }

            // ---- PV: shfl-transpose P (C-frag -> A-frag), then MMA ----
            const int src0 = lr * 4 + (lc >> 1);
            const int src1 = src0 + 2;
            const bool odd = (lc & 1);
#pragma unroll
            for (int ks = 0; ks < 8; ks++) {
                const float b0 = __shfl_sync(0xffffffffu, sc[ks][0], src0);
                const float b1 = __shfl_sync(0xffffffffu, sc[ks][1], src0);
                const float b2 = __shfl_sync(0xffffffffu, sc[ks][2], src0);
                const float b3 = __shfl_sync(0xffffffffu, sc[ks][3], src0);
                const float c0 = __shfl_sync(0xffffffffu, sc[ks][0], src1);
                const float c1 = __shfl_sync(0xffffffffu, sc[ks][1], src1);
                const float c2 = __shfl_sync(0xffffffffu, sc[ks][2], src1);
                const float c3 = __shfl_sync(0xffffffffu, sc[ks][3], src1);
                uint32_t pf[4];
                pf[0] = f2tf32(odd ? b1 : b0);
                pf[1] = f2tf32(odd ? b3 : b2);
                pf[2] = f2tf32(odd ? c1 : c0);
                pf[3] = f2tf32(odd ? c3 : c2);

                const int kk = ks * 8;
#pragma unroll
                for (int nf = 0; nf < 16; nf++) {
                    const int c = nf * 8 + lr;
                    uint32_t vf[2];
                    vf[0] = Vb[(kk + lc) * AVS + c];
                    vf[1] = Vb[(kk + lc + 4) * AVS + c];
                    mma_tf32(o[nf], pf, vf, o[nf]);
                }
            }
        }
    }
#undef ATTN_ISSUE

    // ---- epilogue: normalize, round to tf32, store ----
    const float i0 = 1.0f / l0;
    const float i1 = 1.0f / l1;
#pragma unroll
    for (int nf = 0; nf < 16; nf++) {
        const int c = h * HEAD_DIM + nf * 8 + 2 * lc;
        *(float2*)(g_attn + (size_t)row0 * O_DIM + c) =
            make_float2(roundtf(o[nf][0] * i0), roundtf(o[nf][1] * i0));
        *(float2*)(g_attn + (size_t)(row0 + 8) * O_DIM + c) =
            make_float2(roundtf(o[nf][2] * i1), roundtf(o[nf][3] * i1));
    }
}

// ---------------------------------------------------------------------------
// Launch
// ---------------------------------------------------------------------------
extern "C" void kernel_launch(void* const* d_in, const int* in_sizes, int n_in,
                              void* d_out, int out_size)
{
    const int*   positions = (const int*)d_in[0];
    const float* hidden    = (const float*)d_in[1];
    const float* w_qkv     = (const float*)d_in[2];
    const float* w_o       = (const float*)d_in[3];
    float*       out       = (float*)d_out;

    float *qkv_ptr, *attn_ptr, *hid_ptr, *wqkv_ptr, *wo_ptr;
    cudaGetSymbolAddress((void**)&qkv_ptr,  g_qkv);
    cudaGetSymbolAddress((void**)&attn_ptr, g_attn);
    cudaGetSymbolAddress((void**)&hid_ptr,  g_hid_r);
    cudaGetSymbolAddress((void**)&wqkv_ptr, g_wqkv_r);
    cudaGetSymbolAddress((void**)&wo_ptr,   g_wo_r);

    static int cfg = 0;
    if (!cfg) {
        cudaFuncSetAttribute(gemm_tf32,
                             cudaFuncAttributeMaxDynamicSharedMemorySize,
                             GEMM_SMEM_BYTES);
        cudaFuncSetAttribute(attn_tc_kernel,
                             cudaFuncAttributeMaxDynamicSharedMemorySize,
                             ATTN_SMEM_BYTES);
        cfg = 1;
    }

    // 0) tf32 pre-round of GEMM inputs
    round_tf32_kernel<<<(T_SEQ * HIDDEN) / 1024, 256>>>(
        (const float4*)hidden, (float4*)hid_ptr);
    round_tf32_kernel<<<(HIDDEN * QKV_N) / 1024, 256>>>(
        (const float4*)w_qkv, (float4*)wqkv_ptr);
    round_tf32_kernel<<<(O_DIM * HIDDEN) / 1024, 256>>>(
        (const float4*)w_o, (float4*)wo_ptr);

    // 1) QKV projection
    gemm_tf32<<<dim3(QKV_N / 128, T_SEQ / 128), 256, GEMM_SMEM_BYTES>>>(
        hid_ptr, wqkv_ptr, qkv_ptr, T_SEQ, QKV_N, HIDDEN);

    // 2) mRoPE + V rounding
    rope_kernel<<<dim3(T_SEQ, N_HEADS + 2 * N_KV), 64>>>(positions);

    // 3) Causal flash attention (warp-per-rows tensor-core)
    attn_tc_kernel<<<dim3(T_SEQ / 128, N_HEADS), 256, ATTN_SMEM_BYTES>>>();

    // 4) Output projection
    gemm_tf32<<<dim3(O_DIM / 128, T_SEQ / 128), 256, GEMM_SMEM_BYTES>>>(
        attn_ptr, wo_ptr, out, T_SEQ, O_DIM, HIDDEN);
}